// round 14
// baseline (speedup 1.0000x reference)
#include <cuda_runtime.h>
#include <cuda_fp16.h>

#define NQ   16384
#define NKV  256
#define CH   64
#define MAXB 8
#define CVSPLIT 16

typedef unsigned long long u64;
typedef unsigned int u32;

__device__ __forceinline__ u32 pack_h2(float lo, float hi) {
    u32 r; asm("cvt.rn.f16x2.f32 %0, %1, %2;" : "=r"(r) : "f"(hi), "f"(lo)); return r;
}
__device__ __forceinline__ u32 smem_u32(const void* p) {
    u32 a; asm("{ .reg .u64 t; cvta.to.shared.u64 t, %1; cvt.u32.u64 %0, t; }" : "=r"(a) : "l"(p));
    return a;
}
__device__ __forceinline__ void ldsm4(u32& r0, u32& r1, u32& r2, u32& r3, u32 addr) {
    asm volatile("ldmatrix.sync.aligned.m8n8.x4.shared.b16 {%0,%1,%2,%3}, [%4];"
        : "=r"(r0), "=r"(r1), "=r"(r2), "=r"(r3) : "r"(addr));
}
__device__ __forceinline__ void ldsm4t(u32& r0, u32& r1, u32& r2, u32& r3, u32 addr) {
    asm volatile("ldmatrix.sync.aligned.m8n8.x4.trans.shared.b16 {%0,%1,%2,%3}, [%4];"
        : "=r"(r0), "=r"(r1), "=r"(r2), "=r"(r3) : "r"(addr));
}
__device__ __forceinline__ void mma16816(float* c, const u32* a, u32 b0, u32 b1) {
    asm volatile("mma.sync.aligned.m16n8k16.row.col.f32.f16.f16.f32 "
        "{%0,%1,%2,%3}, {%4,%5,%6,%7}, {%8,%9}, {%0,%1,%2,%3};"
        : "+f"(c[0]), "+f"(c[1]), "+f"(c[2]), "+f"(c[3])
        : "r"(a[0]), "r"(a[1]), "r"(a[2]), "r"(a[3]), "r"(b0), "r"(b1));
}
__device__ __forceinline__ u32 ex2_h2(u32 s) {
    u32 d; asm("ex2.approx.f16x2 %0, %1;" : "=r"(d) : "r"(s)); return d;
}
#define CP_ASYNC16(sm, gp) \
    asm volatile("cp.async.cg.shared.global [%0], [%1], 16;" :: "r"(sm), "l"(gp) : "memory")
#define CP_COMMIT()   asm volatile("cp.async.commit_group;" ::: "memory")
#define CP_WAIT0()    asm volatile("cp.async.wait_group 0;" ::: "memory")
#define CP_WAIT1()    asm volatile("cp.async.wait_group 1;" ::: "memory")

// Scratch (no cudaMalloc allowed)
__device__ float  g_part[CVSPLIT * MAXB * NKV * CH];  // conv partials (8.4MB)
__device__ __half g_kh [MAXB * NKV * CH];             // K fp16 [tok][ch]
__device__ __half g_vh [MAXB * NKV * CH];             // V fp16 [tok][ch]
__device__ __half g_whl[64 * 9216];                   // W hi/lo, smem-image per pos (1.2MB)

// ---------------------------------------------------------------------------
// K0: W hi/lo precompute -> padded smem image. pos p: [hi 64x72][lo 64x72].
// grid 256: block = quarter of a position (16 rows).
// ---------------------------------------------------------------------------
__global__ __launch_bounds__(256) void wprep_kernel(const float* __restrict__ Wsr)
{
    const int p  = blockIdx.x >> 2;
    const int qr = blockIdx.x & 3;          // row quarter (16 rows)
    const int tid = threadIdx.x;
    // 16 rows x 64 cols = 1024 floats = 256 float4, one per thread
    const int row = qr * 16 + (tid >> 4);
    const int c4  = tid & 15;
    float4 f = __ldg((const float4*)(Wsr + ((size_t)p * 64 + row) * 64) + c4);
    __half2 h01 = __floats2half2_rn(f.x, f.y);
    __half2 h23 = __floats2half2_rn(f.z, f.w);
    float2 b01 = __half22float2(h01), b23 = __half22float2(h23);
    __half* dst = g_whl + (size_t)p * 9216;
    int o = row * 72 + c4 * 4;
    *(__half2*)(dst + o)     = h01;
    *(__half2*)(dst + o + 2) = h23;
    *(__half2*)(dst + 4608 + o)     = __floats2half2_rn(f.x - b01.x, f.y - b01.y);
    *(__half2*)(dst + 4608 + o + 2) = __floats2half2_rn(f.z - b23.x, f.w - b23.y);
}

// ---------------------------------------------------------------------------
// K1: conv via mma split-fp16 (3 terms). W via double-buffered cp.async from
// precomputed g_whl; A (x) converted in-kernel. smem 46KB -> 4 CTAs/SM.
// ---------------------------------------------------------------------------
#define CV_AHI 0
#define CV_ALO 4608
#define CV_W0  9216             // W buffer: [hi 9216B][lo 9216B]
#define CV_WBUF 18432
#define CV_SMEM (9216 + 2 * CV_WBUF)   // 46080

__global__ __launch_bounds__(256) void conv_kernel(
    const float* __restrict__ x)
{
    extern __shared__ char smc[];
    const u32 sb = smem_u32(smc);
    const int tid = threadIdx.x;
    const int wid = tid >> 5;
    const int l   = tid & 31;
    const int rt  = wid >> 2;
    const int ngg = wid & 3;

    const int split = blockIdx.x & 15;
    const int tile  = blockIdx.x >> 4;
    const int i     = split >> 1;
    const int j0    = (split & 1) * 4;

    const u32 offA  = (l & 15) * 144 + (l >> 4) * 16;
    const u32 offBt = ((l & 7) + ((l >> 3) & 1) * 8) * 144 + (l >> 4) * 16;

    float C[2][4] = {{0.f,0.f,0.f,0.f},{0.f,0.f,0.f,0.f}};

    const int stok = tid >> 3;
    const int sch  = (tid & 7) * 8;
    const int gtok = tile * 32 + stok;
    const int b  = gtok >> 8;
    const int rm = gtok & 255;
    const int oh = rm >> 4, ow = rm & 15;
    const float4* xbase = (const float4*)(x +
        ((size_t)(b * 128 + oh * 8 + i) * 128 + ow * 8 + j0) * CH + sch);
    const __half* wsrc = g_whl + (size_t)(i * 8 + j0) * 9216;

    // per-thread cp.async chunk: 1024 chunks/iter -> 4 each
    // idx: bit9 = hi/lo region, bits3..8 = row, bits0..2 = 16B col chunk
    auto issueW = [&](int j, int buf) {
        const __half* src = wsrc + (size_t)j * 9216;
        u32 dst = sb + CV_W0 + buf * CV_WBUF;
        #pragma unroll
        for (int it = 0; it < 4; it++) {
            int idx = tid + it * 256;
            int reg = idx >> 9;              // 0 hi, 1 lo
            int row = (idx >> 3) & 63;
            int k   = idx & 7;
            CP_ASYNC16(dst + reg * 9216 + row * 144 + k * 16,
                       src + reg * 4608 + row * 72 + k * 8);
        }
        CP_COMMIT();
    };

    float4 pA0, pA1;
    pA0 = __ldg(xbase); pA1 = __ldg(xbase + 1);
    issueW(0, 0);

    #pragma unroll 1
    for (int j = 0; j < 4; j++) {
        // stage A(j)
        {
            __half2 h01 = __floats2half2_rn(pA0.x, pA0.y);
            __half2 h23 = __floats2half2_rn(pA0.z, pA0.w);
            __half2 h45 = __floats2half2_rn(pA1.x, pA1.y);
            __half2 h67 = __floats2half2_rn(pA1.z, pA1.w);
            float2 b01 = __half22float2(h01), b23 = __half22float2(h23);
            float2 b45 = __half22float2(h45), b67 = __half22float2(h67);
            int o = (stok * 72 + sch) * 2;
            *(__half2*)(smc + CV_AHI + o)      = h01;
            *(__half2*)(smc + CV_AHI + o + 4)  = h23;
            *(__half2*)(smc + CV_AHI + o + 8)  = h45;
            *(__half2*)(smc + CV_AHI + o + 12) = h67;
            *(__half2*)(smc + CV_ALO + o)      = __floats2half2_rn(pA0.x - b01.x, pA0.y - b01.y);
            *(__half2*)(smc + CV_ALO + o + 4)  = __floats2half2_rn(pA0.z - b23.x, pA0.w - b23.y);
            *(__half2*)(smc + CV_ALO + o + 8)  = __floats2half2_rn(pA1.x - b45.x, pA1.y - b45.y);
            *(__half2*)(smc + CV_ALO + o + 12) = __floats2half2_rn(pA1.z - b67.x, pA1.w - b67.y);
        }
        if (j < 3) {
            pA0 = __ldg(xbase + (j + 1) * 16);
            pA1 = __ldg(xbase + (j + 1) * 16 + 1);
            issueW(j + 1, (j + 1) & 1);
            CP_WAIT1();            // W(j) landed, W(j+1) in flight
        } else {
            CP_WAIT0();
        }
        __syncthreads();

        const u32 wb = sb + CV_W0 + (j & 1) * CV_WBUF;
        u32 axh[4][4], axl[4][4];
        #pragma unroll
        for (int kc = 0; kc < 4; kc++) {
            ldsm4(axh[kc][0], axh[kc][1], axh[kc][2], axh[kc][3],
                  sb + CV_AHI + rt * 16 * 144 + offA + kc * 32);
            ldsm4(axl[kc][0], axl[kc][1], axl[kc][2], axl[kc][3],
                  sb + CV_ALO + rt * 16 * 144 + offA + kc * 32);
        }
        #pragma unroll
        for (int kc = 0; kc < 4; kc++) {
            u32 h0, h1, h2, h3, q0, q1, q2, q3;
            ldsm4t(h0, h1, h2, h3, wb + offBt + kc * 16 * 144 + ngg * 32);
            ldsm4t(q0, q1, q2, q3, wb + 9216 + offBt + kc * 16 * 144 + ngg * 32);
            mma16816(C[0], axh[kc], h0, h1);
            mma16816(C[1], axh[kc], h2, h3);
            mma16816(C[0], axl[kc], h0, h1);
            mma16816(C[1], axl[kc], h2, h3);
            mma16816(C[0], axh[kc], q0, q1);
            mma16816(C[1], axh[kc], q2, q3);
        }
        __syncthreads();
    }

    {
        int tl0 = rt * 16 + (l >> 2);
        int gt0 = tile * 32 + tl0;
        int gt1 = gt0 + 8;
        float* gp = g_part + (size_t)split * (MAXB * NKV * CH);
        int col0 = ngg * 16 + (l & 3) * 2;
        *(float2*)(gp + (size_t)gt0 * CH + col0)     = make_float2(C[0][0], C[0][1]);
        *(float2*)(gp + (size_t)gt0 * CH + col0 + 8) = make_float2(C[1][0], C[1][1]);
        *(float2*)(gp + (size_t)gt1 * CH + col0)     = make_float2(C[0][2], C[0][3]);
        *(float2*)(gp + (size_t)gt1 * CH + col0 + 8) = make_float2(C[1][2], C[1][3]);
    }
}

// ---------------------------------------------------------------------------
// K2: K-split reduce + bias + LayerNorm + K/V proj. 128 blocks x 16 tokens.
// ---------------------------------------------------------------------------
__global__ __launch_bounds__(256) void lnkv_kernel(
    const float* __restrict__ bsr,
    const float* __restrict__ gamma, const float* __restrict__ beta,
    const float* __restrict__ Wk, const float* __restrict__ bk,
    const float* __restrict__ Wv, const float* __restrict__ bv)
{
    __shared__ float sW[8192];
    __shared__ float sA[16 * 65];
    const int tid = threadIdx.x;
    const int tokbase = blockIdx.x * 16;

    {
        float4* d = (float4*)sW;
        const float4* k4 = (const float4*)Wk;
        const float4* v4 = (const float4*)Wv;
        #pragma unroll
        for (int e = 0; e < 4; e++) d[e * 256 + tid] = __ldg(k4 + e * 256 + tid);
        #pragma unroll
        for (int e = 0; e < 4; e++) d[1024 + e * 256 + tid] = __ldg(v4 + e * 256 + tid);
    }
    {
        int row = tid >> 4, c4 = tid & 15;
        size_t off = ((size_t)(tokbase + row) * CH + c4 * 4) / 4;
        float4 v = __ldg((const float4*)bsr + c4);
        #pragma unroll
        for (int s = 0; s < CVSPLIT; s++) {
            float4 p = *((const float4*)(g_part + (size_t)s * (MAXB * NKV * CH)) + off);
            v.x += p.x; v.y += p.y; v.z += p.z; v.w += p.w;
        }
        float* a = sA + row * 65 + c4 * 4;
        a[0] = v.x; a[1] = v.y; a[2] = v.z; a[3] = v.w;
    }
    __syncthreads();

    if (tid < 16) {
        float* a = sA + tid * 65;
        float mu = 0.f;
        #pragma unroll
        for (int c = 0; c < 64; c++) mu += a[c];
        mu *= (1.0f / 64.0f);
        float var = 0.f;
        #pragma unroll
        for (int c = 0; c < 64; c++) { float d = a[c] - mu; var += d * d; }
        var *= (1.0f / 64.0f);
        float inv = rsqrtf(var + 1e-5f);
        #pragma unroll
        for (int c = 0; c < 64; c++)
            a[c] = (a[c] - mu) * inv * __ldg(gamma + c) + __ldg(beta + c);
    }
    __syncthreads();

    {
        const int token = tid >> 4, c4 = tid & 15;
        const float* ar = sA + token * 65;
        const float4* Wk4 = (const float4*)sW;
        const float4* Wv4 = (const float4*)sW + 1024;
        float4 ka = __ldg((const float4*)bk + c4);
        float4 va = __ldg((const float4*)bv + c4);
        #pragma unroll 4
        for (int j = 0; j < 64; j++) {
            float  av = ar[j];
            float4 wk = Wk4[j * 16 + c4];
            float4 wv = Wv4[j * 16 + c4];
            ka.x += av * wk.x; ka.y += av * wk.y; ka.z += av * wk.z; ka.w += av * wk.w;
            va.x += av * wv.x; va.y += av * wv.y; va.z += av * wv.z; va.w += av * wv.w;
        }
        const int gtok = tokbase + token;
        __half2* kp = (__half2*)(g_kh + (size_t)gtok * CH + c4 * 4);
        kp[0] = __floats2half2_rn(ka.x, ka.y);
        kp[1] = __floats2half2_rn(ka.z, ka.w);
        __half2* vp = (__half2*)(g_vh + (size_t)gtok * CH + c4 * 4);
        vp[0] = __floats2half2_rn(va.x, va.y);
        vp[1] = __floats2half2_rn(va.z, va.w);
    }
}

// ---------------------------------------------------------------------------
// K3: mma fused attention; 128q/CTA, 512 threads = 8 rowtiles x 2 kv-halves.
// Each warp reads HALF of K/V (8 c-iters). Partial O/l exchanged via the dead
// K smem region; GEMM4 done by kv-half-0 warps.
// ---------------------------------------------------------------------------
#define SM_K    0            // K [256][72] fp16 36864B (reused: O exchange, stride 66 f32)
#define SM_V    36864        // V  [256][72] fp16  36864B
#define SM_WQ   73728        // Wq [64][72]  fp16  9216B
#define SM_WP   82944        // Wp [64][72]  fp16  9216B
#define SM_LX   92160        // partner l sums: 128 f32
#define SM_TOTAL 92672

#define QSCALE 0.1803368801f   // 0.125 * log2(e)

__global__ __launch_bounds__(512, 1) void attn_kernel(
    const float* __restrict__ x,
    const float* __restrict__ Wq, const float* __restrict__ bq,
    const float* __restrict__ Wp, const float* __restrict__ bp,
    float* __restrict__ out)
{
    extern __shared__ char smem[];
    const u32 sb = smem_u32(smem);
    const int tid = threadIdx.x;
    const int wid = tid >> 5;
    const int l   = tid & 31;
    const int rt  = wid & 7;     // rowtile: rows 16*rt..16*rt+15
    const int kh  = wid >> 3;    // kv half: c-iters kh*8..kh*8+7
    const int wrow = rt * 16;

    const int b = blockIdx.x >> 7;
    const int qbase = blockIdx.x * 128;

    // 1. cp.async K/V (2048 chunks / 512 thr = 4 each)
    {
        const __half* ks = g_kh + (size_t)b * NKV * CH;
        const __half* vs = g_vh + (size_t)b * NKV * CH;
        #pragma unroll
        for (int it = 0; it < 4; it++) {
            int idx = tid + it * 512;
            int row = idx >> 3, sub = idx & 7;
            u32 so = (row * 72 + sub * 8) * 2;
            CP_ASYNC16(sb + SM_K + so, ks + idx * 8);
            CP_ASYNC16(sb + SM_V + so, vs + idx * 8);
        }
        CP_COMMIT();
    }
    // 2. stage Wq/Wp (2048 float4 / 512 = 4 each)
    {
        #pragma unroll
        for (int it = 0; it < 4; it++) {
            int idx = tid + it * 512;
            int sel = idx >> 10;
            int r   = (idx >> 4) & 63, c4 = idx & 15;
            const float4* src = (const float4*)(sel ? Wp : Wq);
            float4 f = __ldg(src + (idx & 1023));
            __half2* d = (__half2*)(smem + (sel ? SM_WP : SM_WQ) + (r * 72 + c4 * 4) * 2);
            d[0] = __floats2half2_rn(f.x, f.y);
            d[1] = __floats2half2_rn(f.z, f.w);
        }
    }

    const u32 offA  = (l & 15) * 144 + (l >> 4) * 16;
    const u32 offBk = ((l & 7) + (l >> 4) * 8) * 144 + ((l >> 3) & 1) * 16;
    const u32 offBt = ((l & 7) + ((l >> 3) & 1) * 8) * 144 + (l >> 4) * 16;

    const u32 aK  = sb + SM_K  + offBk;
    const u32 aV  = sb + SM_V  + offBt;
    const u32 aWQ = sb + SM_WQ + offBt;
    const u32 aWP = sb + SM_WP + offBt;

    // 3. X A-frags direct from gmem (pair warps duplicate their rows)
    u32 ax[4][4];
    {
        const int r0 = qbase + wrow + (l >> 2);
        const int c0 = (l & 3) * 2;
        const float* x0 = x + (size_t)r0 * CH + c0;
        const float* x1 = x + (size_t)(r0 + 8) * CH + c0;
        #pragma unroll
        for (int kc = 0; kc < 4; kc++) {
            float2 f00 = __ldg((const float2*)(x0 + kc * 16));
            float2 f10 = __ldg((const float2*)(x1 + kc * 16));
            float2 f01 = __ldg((const float2*)(x0 + kc * 16 + 8));
            float2 f11 = __ldg((const float2*)(x1 + kc * 16 + 8));
            ax[kc][0] = pack_h2(f00.x, f00.y);
            ax[kc][1] = pack_h2(f10.x, f10.y);
            ax[kc][2] = pack_h2(f01.x, f01.y);
            ax[kc][3] = pack_h2(f11.x, f11.y);
        }
    }
    __syncthreads();    // Wq/Wp visible

    // 4. GEMM1: Q = (X @ Wq + bq) * QSCALE (duplicated across kv-half pair)
    u32 aQ[4][4];
    #pragma unroll
    for (int ng = 0; ng < 4; ng++) {
        float C0[4] = {0.f, 0.f, 0.f, 0.f};
        float C1[4] = {0.f, 0.f, 0.f, 0.f};
        #pragma unroll
        for (int kc = 0; kc < 4; kc++) {
            u32 b0, b1, b2, b3;
            ldsm4t(b0, b1, b2, b3, aWQ + kc * 16 * 144 + ng * 32);
            mma16816(C0, ax[kc], b0, b1);
            mma16816(C1, ax[kc], b2, b3);
        }
        int col0 = ng * 16 + (l & 3) * 2;
        float q00 = __ldg(bq + col0),     q01 = __ldg(bq + col0 + 1);
        float q10 = __ldg(bq + col0 + 8), q11 = __ldg(bq + col0 + 9);
        aQ[ng][0] = pack_h2((C0[0] + q00) * QSCALE, (C0[1] + q01) * QSCALE);
        aQ[ng][1] = pack_h2((C0[2] + q00) * QSCALE, (C0[3] + q01) * QSCALE);
        aQ[ng][2] = pack_h2((C1[0] + q10) * QSCALE, (C1[1] + q11) * QSCALE);
        aQ[ng][3] = pack_h2((C1[2] + q10) * QSCALE, (C1[3] + q11) * QSCALE);
    }

    CP_WAIT0();
    __syncthreads();    // K/V visible

    // 5. mainloop over this warp's kv half (8 c-iters)
    float O[8][4];
    #pragma unroll
    for (int m = 0; m < 8; m++)
        { O[m][0] = 0.f; O[m][1] = 0.f; O[m][2] = 0.f; O[m][3] = 0.f; }
    float ls0 = 0.f, ls1 = 0.f;

    #pragma unroll 2
    for (int cc = 0; cc < 8; cc++) {
        const int c = kh * 8 + cc;
        const u32 kbase = aK + c * 16 * 144;
        const u32 vbase = aV + c * 16 * 144;
        u32 vb[4][4];
        #pragma unroll
        for (int ng = 0; ng < 4; ng++)
            ldsm4t(vb[ng][0], vb[ng][1], vb[ng][2], vb[ng][3], vbase + ng * 32);

        float S0[4] = {0.f, 0.f, 0.f, 0.f};
        float S1[4] = {0.f, 0.f, 0.f, 0.f};
        #pragma unroll
        for (int kc = 0; kc < 4; kc++) {
            u32 b0, b1, b2, b3;
            ldsm4(b0, b1, b2, b3, kbase + kc * 32);
            mma16816(S0, aQ[kc], b0, b1);
            mma16816(S1, aQ[kc], b2, b3);
        }
        u32 pA[4];
        pA[0] = ex2_h2(pack_h2(S0[0], S0[1]));
        pA[1] = ex2_h2(pack_h2(S0[2], S0[3]));
        pA[2] = ex2_h2(pack_h2(S1[0], S1[1]));
        pA[3] = ex2_h2(pack_h2(S1[2], S1[3]));
        {
            __half2 s02 = __hadd2(*(__half2*)&pA[0], *(__half2*)&pA[2]);
            __half2 s13 = __hadd2(*(__half2*)&pA[1], *(__half2*)&pA[3]);
            float2 f0 = __half22float2(s02);
            float2 f1 = __half22float2(s13);
            ls0 += f0.x + f0.y;
            ls1 += f1.x + f1.y;
        }
        #pragma unroll
        for (int ng = 0; ng < 4; ng++) {
            mma16816(O[2 * ng],     pA, vb[ng][0], vb[ng][1]);
            mma16816(O[2 * ng + 1], pA, vb[ng][2], vb[ng][3]);
        }
    }

    // reduce l within warp (columns)
    ls0 += __shfl_xor_sync(0xffffffffu, ls0, 1);
    ls0 += __shfl_xor_sync(0xffffffffu, ls0, 2);
    ls1 += __shfl_xor_sync(0xffffffffu, ls1, 1);
    ls1 += __shfl_xor_sync(0xffffffffu, ls1, 2);

    const int row0s = wrow + (l >> 2);
    const int row1s = row0s + 8;
    float* OX = (float*)(smem + SM_K);          // stride 66 f32
    float* LX = (float*)(smem + SM_LX);

    __syncthreads();    // everyone done reading K region

    // 6. kv-half-1 warps publish partial O and l
    if (kh == 1) {
        #pragma unroll
        for (int m = 0; m < 8; m++) {
            int col = (m >> 1) * 16 + (m & 1) * 8 + (l & 3) * 2;
            *(float2*)(OX + row0s * 66 + col) = make_float2(O[m][0], O[m][1]);
            *(float2*)(OX + row1s * 66 + col) = make_float2(O[m][2], O[m][3]);
        }
        if ((l & 3) == 0) { LX[row0s] = ls0; LX[row1s] = ls1; }
    }
    __syncthreads();

    // 7. kv-half-0 warps: combine, normalize, GEMM4, store
    if (kh == 0) {
        #pragma unroll
        for (int m = 0; m < 8; m++) {
            int col = (m >> 1) * 16 + (m & 1) * 8 + (l & 3) * 2;
            float2 a0 = *(float2*)(OX + row0s * 66 + col);
            float2 a1 = *(float2*)(OX + row1s * 66 + col);
            O[m][0] += a0.x; O[m][1] += a0.y;
            O[m][2] += a1.x; O[m][3] += a1.y;
        }
        const float rl0 = 1.0f / (ls0 + LX[row0s]);
        const float rl1 = 1.0f / (ls1 + LX[row1s]);

        u32 aO[4][4];
        #pragma unroll
        for (int kc = 0; kc < 4; kc++) {
            aO[kc][0] = pack_h2(O[2 * kc][0] * rl0,     O[2 * kc][1] * rl0);
            aO[kc][1] = pack_h2(O[2 * kc][2] * rl1,     O[2 * kc][3] * rl1);
            aO[kc][2] = pack_h2(O[2 * kc + 1][0] * rl0, O[2 * kc + 1][1] * rl0);
            aO[kc][3] = pack_h2(O[2 * kc + 1][2] * rl1, O[2 * kc + 1][3] * rl1);
        }

        const int row0 = qbase + wrow + (l >> 2);
        #pragma unroll
        for (int ng = 0; ng < 4; ng++) {
            float C0[4] = {0.f, 0.f, 0.f, 0.f};
            float C1[4] = {0.f, 0.f, 0.f, 0.f};
            #pragma unroll
            for (int kc = 0; kc < 4; kc++) {
                u32 b0, b1, b2, b3;
                ldsm4t(b0, b1, b2, b3, aWP + kc * 16 * 144 + ng * 32);
                mma16816(C0, aO[kc], b0, b1);
                mma16816(C1, aO[kc], b2, b3);
            }
            int col0 = ng * 16 + (l & 3) * 2;
            float p00 = __ldg(bp + col0),     p01 = __ldg(bp + col0 + 1);
            float p10 = __ldg(bp + col0 + 8), p11 = __ldg(bp + col0 + 9);
            float2* o0 = (float2*)(out + (size_t)row0 * CH + col0);
            float2* o1 = (float2*)(out + (size_t)(row0 + 8) * CH + col0);
            o0[0] = make_float2(C0[0] + p00, C0[1] + p01);
            o0[4] = make_float2(C1[0] + p10, C1[1] + p11);
            o1[0] = make_float2(C0[2] + p00, C0[3] + p01);
            o1[4] = make_float2(C1[2] + p10, C1[3] + p11);
        }
    }
}

// ---------------------------------------------------------------------------
extern "C" void kernel_launch(void* const* d_in, const int* in_sizes, int n_in,
                              void* d_out, int out_size)
{
    const float* x     = (const float*)d_in[0];
    const float* Wq    = (const float*)d_in[1];
    const float* bq    = (const float*)d_in[2];
    const float* Wk    = (const float*)d_in[3];
    const float* bk    = (const float*)d_in[4];
    const float* Wv    = (const float*)d_in[5];
    const float* bv    = (const float*)d_in[6];
    const float* Wsr   = (const float*)d_in[7];
    const float* bsr   = (const float*)d_in[8];
    const float* gamma = (const float*)d_in[9];
    const float* beta  = (const float*)d_in[10];
    const float* Wp    = (const float*)d_in[11];
    const float* bp    = (const float*)d_in[12];
    float* out = (float*)d_out;

    int B = in_sizes[0] / (NQ * CH);
    if (B > MAXB) B = MAXB;

    cudaFuncSetAttribute(conv_kernel, cudaFuncAttributeMaxDynamicSharedMemorySize, CV_SMEM);
    cudaFuncSetAttribute(attn_kernel, cudaFuncAttributeMaxDynamicSharedMemorySize, SM_TOTAL);

    wprep_kernel<<<256, 256>>>(Wsr);
    conv_kernel<<<B * 8 * 16, 256, CV_SMEM>>>(x);
    lnkv_kernel<<<B * 16, 256>>>(bsr, gamma, beta, Wk, bk, Wv, bv);
    attn_kernel<<<B * 128, 512, SM_TOTAL>>>(x, Wq, bq, Wp, bp, out);
}

// round 15
// speedup vs baseline: 1.3455x; 1.3455x over previous
#include <cuda_runtime.h>
#include <cuda_fp16.h>

#define NQ   16384
#define NKV  256
#define CH   64
#define MAXB 8
#define CVSPLIT 16

typedef unsigned long long u64;
typedef unsigned int u32;

__device__ __forceinline__ u32 pack_h2(float lo, float hi) {
    u32 r; asm("cvt.rn.f16x2.f32 %0, %1, %2;" : "=r"(r) : "f"(hi), "f"(lo)); return r;
}
__device__ __forceinline__ u32 smem_u32(const void* p) {
    u32 a; asm("{ .reg .u64 t; cvta.to.shared.u64 t, %1; cvt.u32.u64 %0, t; }" : "=r"(a) : "l"(p));
    return a;
}
__device__ __forceinline__ void ldsm4(u32& r0, u32& r1, u32& r2, u32& r3, u32 addr) {
    asm volatile("ldmatrix.sync.aligned.m8n8.x4.shared.b16 {%0,%1,%2,%3}, [%4];"
        : "=r"(r0), "=r"(r1), "=r"(r2), "=r"(r3) : "r"(addr));
}
__device__ __forceinline__ void ldsm4t(u32& r0, u32& r1, u32& r2, u32& r3, u32 addr) {
    asm volatile("ldmatrix.sync.aligned.m8n8.x4.trans.shared.b16 {%0,%1,%2,%3}, [%4];"
        : "=r"(r0), "=r"(r1), "=r"(r2), "=r"(r3) : "r"(addr));
}
__device__ __forceinline__ void mma16816(float* c, const u32* a, u32 b0, u32 b1) {
    asm volatile("mma.sync.aligned.m16n8k16.row.col.f32.f16.f16.f32 "
        "{%0,%1,%2,%3}, {%4,%5,%6,%7}, {%8,%9}, {%0,%1,%2,%3};"
        : "+f"(c[0]), "+f"(c[1]), "+f"(c[2]), "+f"(c[3])
        : "r"(a[0]), "r"(a[1]), "r"(a[2]), "r"(a[3]), "r"(b0), "r"(b1));
}
__device__ __forceinline__ u32 ex2_h2(u32 s) {
    u32 d; asm("ex2.approx.f16x2 %0, %1;" : "=r"(d) : "r"(s)); return d;
}
#define CP_ASYNC16(sm, gp) \
    asm volatile("cp.async.cg.shared.global [%0], [%1], 16;" :: "r"(sm), "l"(gp) : "memory")
#define CP_COMMIT()   asm volatile("cp.async.commit_group;" ::: "memory")
#define CP_WAIT0()    asm volatile("cp.async.wait_group 0;" ::: "memory")
#define CP_WAIT1()    asm volatile("cp.async.wait_group 1;" ::: "memory")

// Scratch (no cudaMalloc allowed)
__device__ float  g_part[CVSPLIT * MAXB * NKV * CH];  // conv partials (8.4MB)
__device__ __half g_kh [MAXB * NKV * CH];             // K fp16 [tok][ch]
__device__ __half g_vh [MAXB * NKV * CH];             // V fp16 [tok][ch]
__device__ __half g_whl[64 * 9216];                   // W hi/lo smem image (1.2MB)

// ---------------------------------------------------------------------------
// K0: W hi/lo precompute -> padded smem image. pos p: [hi 64x72][lo 64x72].
// ---------------------------------------------------------------------------
__global__ __launch_bounds__(256) void wprep_kernel(const float* __restrict__ Wsr)
{
    const int p  = blockIdx.x >> 2;
    const int qr = blockIdx.x & 3;
    const int tid = threadIdx.x;
    const int row = qr * 16 + (tid >> 4);
    const int c4  = tid & 15;
    float4 f = __ldg((const float4*)(Wsr + ((size_t)p * 64 + row) * 64) + c4);
    __half2 h01 = __floats2half2_rn(f.x, f.y);
    __half2 h23 = __floats2half2_rn(f.z, f.w);
    float2 b01 = __half22float2(h01), b23 = __half22float2(h23);
    __half* dst = g_whl + (size_t)p * 9216;
    int o = row * 72 + c4 * 4;
    *(__half2*)(dst + o)     = h01;
    *(__half2*)(dst + o + 2) = h23;
    *(__half2*)(dst + 4608 + o)     = __floats2half2_rn(f.x - b01.x, f.y - b01.y);
    *(__half2*)(dst + 4608 + o + 2) = __floats2half2_rn(f.z - b23.x, f.w - b23.y);
}

// ---------------------------------------------------------------------------
// K1: conv via mma split-fp16 (3 terms); W double-buffered cp.async from g_whl.
// ---------------------------------------------------------------------------
#define CV_AHI 0
#define CV_ALO 4608
#define CV_W0  9216
#define CV_WBUF 18432
#define CV_SMEM (9216 + 2 * CV_WBUF)   // 46080

__global__ __launch_bounds__(256) void conv_kernel(
    const float* __restrict__ x)
{
    extern __shared__ char smc[];
    const u32 sb = smem_u32(smc);
    const int tid = threadIdx.x;
    const int wid = tid >> 5;
    const int l   = tid & 31;
    const int rt  = wid >> 2;
    const int ngg = wid & 3;

    const int split = blockIdx.x & 15;
    const int tile  = blockIdx.x >> 4;
    const int i     = split >> 1;
    const int j0    = (split & 1) * 4;

    const u32 offA  = (l & 15) * 144 + (l >> 4) * 16;
    const u32 offBt = ((l & 7) + ((l >> 3) & 1) * 8) * 144 + (l >> 4) * 16;

    float C[2][4] = {{0.f,0.f,0.f,0.f},{0.f,0.f,0.f,0.f}};

    const int stok = tid >> 3;
    const int sch  = (tid & 7) * 8;
    const int gtok = tile * 32 + stok;
    const int b  = gtok >> 8;
    const int rm = gtok & 255;
    const int oh = rm >> 4, ow = rm & 15;
    const float4* xbase = (const float4*)(x +
        ((size_t)(b * 128 + oh * 8 + i) * 128 + ow * 8 + j0) * CH + sch);
    const __half* wsrc = g_whl + (size_t)(i * 8 + j0) * 9216;

    auto issueW = [&](int j, int buf) {
        const __half* src = wsrc + (size_t)j * 9216;
        u32 dst = sb + CV_W0 + buf * CV_WBUF;
        #pragma unroll
        for (int it = 0; it < 4; it++) {
            int idx = tid + it * 256;
            int reg = idx >> 9;
            int row = (idx >> 3) & 63;
            int k   = idx & 7;
            CP_ASYNC16(dst + reg * 9216 + row * 144 + k * 16,
                       src + reg * 4608 + row * 72 + k * 8);
        }
        CP_COMMIT();
    };

    float4 pA0, pA1;
    pA0 = __ldg(xbase); pA1 = __ldg(xbase + 1);
    issueW(0, 0);

    #pragma unroll 1
    for (int j = 0; j < 4; j++) {
        {
            __half2 h01 = __floats2half2_rn(pA0.x, pA0.y);
            __half2 h23 = __floats2half2_rn(pA0.z, pA0.w);
            __half2 h45 = __floats2half2_rn(pA1.x, pA1.y);
            __half2 h67 = __floats2half2_rn(pA1.z, pA1.w);
            float2 b01 = __half22float2(h01), b23 = __half22float2(h23);
            float2 b45 = __half22float2(h45), b67 = __half22float2(h67);
            int o = (stok * 72 + sch) * 2;
            *(__half2*)(smc + CV_AHI + o)      = h01;
            *(__half2*)(smc + CV_AHI + o + 4)  = h23;
            *(__half2*)(smc + CV_AHI + o + 8)  = h45;
            *(__half2*)(smc + CV_AHI + o + 12) = h67;
            *(__half2*)(smc + CV_ALO + o)      = __floats2half2_rn(pA0.x - b01.x, pA0.y - b01.y);
            *(__half2*)(smc + CV_ALO + o + 4)  = __floats2half2_rn(pA0.z - b23.x, pA0.w - b23.y);
            *(__half2*)(smc + CV_ALO + o + 8)  = __floats2half2_rn(pA1.x - b45.x, pA1.y - b45.y);
            *(__half2*)(smc + CV_ALO + o + 12) = __floats2half2_rn(pA1.z - b67.x, pA1.w - b67.y);
        }
        if (j < 3) {
            pA0 = __ldg(xbase + (j + 1) * 16);
            pA1 = __ldg(xbase + (j + 1) * 16 + 1);
            issueW(j + 1, (j + 1) & 1);
            CP_WAIT1();
        } else {
            CP_WAIT0();
        }
        __syncthreads();

        const u32 wb = sb + CV_W0 + (j & 1) * CV_WBUF;
        u32 axh[4][4], axl[4][4];
        #pragma unroll
        for (int kc = 0; kc < 4; kc++) {
            ldsm4(axh[kc][0], axh[kc][1], axh[kc][2], axh[kc][3],
                  sb + CV_AHI + rt * 16 * 144 + offA + kc * 32);
            ldsm4(axl[kc][0], axl[kc][1], axl[kc][2], axl[kc][3],
                  sb + CV_ALO + rt * 16 * 144 + offA + kc * 32);
        }
        #pragma unroll
        for (int kc = 0; kc < 4; kc++) {
            u32 h0, h1, h2, h3, q0, q1, q2, q3;
            ldsm4t(h0, h1, h2, h3, wb + offBt + kc * 16 * 144 + ngg * 32);
            ldsm4t(q0, q1, q2, q3, wb + 9216 + offBt + kc * 16 * 144 + ngg * 32);
            mma16816(C[0], axh[kc], h0, h1);
            mma16816(C[1], axh[kc], h2, h3);
            mma16816(C[0], axl[kc], h0, h1);
            mma16816(C[1], axl[kc], h2, h3);
            mma16816(C[0], axh[kc], q0, q1);
            mma16816(C[1], axh[kc], q2, q3);
        }
        __syncthreads();
    }

    {
        int tl0 = rt * 16 + (l >> 2);
        int gt0 = tile * 32 + tl0;
        int gt1 = gt0 + 8;
        float* gp = g_part + (size_t)split * (MAXB * NKV * CH);
        int col0 = ngg * 16 + (l & 3) * 2;
        *(float2*)(gp + (size_t)gt0 * CH + col0)     = make_float2(C[0][0], C[0][1]);
        *(float2*)(gp + (size_t)gt0 * CH + col0 + 8) = make_float2(C[1][0], C[1][1]);
        *(float2*)(gp + (size_t)gt1 * CH + col0)     = make_float2(C[0][2], C[0][3]);
        *(float2*)(gp + (size_t)gt1 * CH + col0 + 8) = make_float2(C[1][2], C[1][3]);
    }
}

// ---------------------------------------------------------------------------
// K2: K-split reduce + bias + LayerNorm + K/V proj. 128 blocks x 16 tokens.
// ---------------------------------------------------------------------------
__global__ __launch_bounds__(256) void lnkv_kernel(
    const float* __restrict__ bsr,
    const float* __restrict__ gamma, const float* __restrict__ beta,
    const float* __restrict__ Wk, const float* __restrict__ bk,
    const float* __restrict__ Wv, const float* __restrict__ bv)
{
    __shared__ float sW[8192];
    __shared__ float sA[16 * 65];
    const int tid = threadIdx.x;
    const int tokbase = blockIdx.x * 16;

    {
        float4* d = (float4*)sW;
        const float4* k4 = (const float4*)Wk;
        const float4* v4 = (const float4*)Wv;
        #pragma unroll
        for (int e = 0; e < 4; e++) d[e * 256 + tid] = __ldg(k4 + e * 256 + tid);
        #pragma unroll
        for (int e = 0; e < 4; e++) d[1024 + e * 256 + tid] = __ldg(v4 + e * 256 + tid);
    }
    {
        int row = tid >> 4, c4 = tid & 15;
        size_t off = ((size_t)(tokbase + row) * CH + c4 * 4) / 4;
        float4 v = __ldg((const float4*)bsr + c4);
        #pragma unroll
        for (int s = 0; s < CVSPLIT; s++) {
            float4 p = *((const float4*)(g_part + (size_t)s * (MAXB * NKV * CH)) + off);
            v.x += p.x; v.y += p.y; v.z += p.z; v.w += p.w;
        }
        float* a = sA + row * 65 + c4 * 4;
        a[0] = v.x; a[1] = v.y; a[2] = v.z; a[3] = v.w;
    }
    __syncthreads();

    if (tid < 16) {
        float* a = sA + tid * 65;
        float mu = 0.f;
        #pragma unroll
        for (int c = 0; c < 64; c++) mu += a[c];
        mu *= (1.0f / 64.0f);
        float var = 0.f;
        #pragma unroll
        for (int c = 0; c < 64; c++) { float d = a[c] - mu; var += d * d; }
        var *= (1.0f / 64.0f);
        float inv = rsqrtf(var + 1e-5f);
        #pragma unroll
        for (int c = 0; c < 64; c++)
            a[c] = (a[c] - mu) * inv * __ldg(gamma + c) + __ldg(beta + c);
    }
    __syncthreads();

    {
        const int token = tid >> 4, c4 = tid & 15;
        const float* ar = sA + token * 65;
        const float4* Wk4 = (const float4*)sW;
        const float4* Wv4 = (const float4*)sW + 1024;
        float4 ka = __ldg((const float4*)bk + c4);
        float4 va = __ldg((const float4*)bv + c4);
        #pragma unroll 4
        for (int j = 0; j < 64; j++) {
            float  av = ar[j];
            float4 wk = Wk4[j * 16 + c4];
            float4 wv = Wv4[j * 16 + c4];
            ka.x += av * wk.x; ka.y += av * wk.y; ka.z += av * wk.z; ka.w += av * wk.w;
            va.x += av * wv.x; va.y += av * wv.y; va.z += av * wv.z; va.w += av * wv.w;
        }
        const int gtok = tokbase + token;
        __half2* kp = (__half2*)(g_kh + (size_t)gtok * CH + c4 * 4);
        kp[0] = __floats2half2_rn(ka.x, ka.y);
        kp[1] = __floats2half2_rn(ka.z, ka.w);
        __half2* vp = (__half2*)(g_vh + (size_t)gtok * CH + c4 * 4);
        vp[0] = __floats2half2_rn(va.x, va.y);
        vp[1] = __floats2half2_rn(va.z, va.w);
    }
}

// ---------------------------------------------------------------------------
// K3: mma fused attention (round-13, best measured); 128q/CTA, 8 warps,
// 2 CTAs/SM, cp.async K/V, hoisted V frags, mainloop unroll 2.
// ---------------------------------------------------------------------------
#define SM_K    0
#define SM_V    36864
#define SM_WQ   73728
#define SM_WP   82944
#define SM_TOTAL 92160

#define QSCALE 0.1803368801f   // 0.125 * log2(e)

__global__ __launch_bounds__(256, 2) void attn_kernel(
    const float* __restrict__ x,
    const float* __restrict__ Wq, const float* __restrict__ bq,
    const float* __restrict__ Wp, const float* __restrict__ bp,
    float* __restrict__ out)
{
    extern __shared__ char smem[];
    const u32 sb = smem_u32(smem);
    const int tid = threadIdx.x;
    const int wid = tid >> 5;
    const int l   = tid & 31;
    const int wrow = wid * 16;

    const int b = blockIdx.x >> 7;
    const int qbase = blockIdx.x * 128;

    {
        const __half* ks = g_kh + (size_t)b * NKV * CH;
        const __half* vs = g_vh + (size_t)b * NKV * CH;
        #pragma unroll
        for (int it = 0; it < 8; it++) {
            int idx = tid + it * 256;
            int row = idx >> 3, sub = idx & 7;
            u32 so = (row * 72 + sub * 8) * 2;
            CP_ASYNC16(sb + SM_K + so, ks + idx * 8);
            CP_ASYNC16(sb + SM_V + so, vs + idx * 8);
        }
        CP_COMMIT();
    }
    {
        #pragma unroll
        for (int it = 0; it < 8; it++) {
            int idx = tid + it * 256;
            int sel = idx >> 10;
            int r   = (idx >> 4) & 63, c4 = idx & 15;
            const float4* src = (const float4*)(sel ? Wp : Wq);
            float4 f = __ldg(src + (idx & 1023));
            __half2* d = (__half2*)(smem + (sel ? SM_WP : SM_WQ) + (r * 72 + c4 * 4) * 2);
            d[0] = __floats2half2_rn(f.x, f.y);
            d[1] = __floats2half2_rn(f.z, f.w);
        }
    }

    const u32 offA  = (l & 15) * 144 + (l >> 4) * 16;
    const u32 offBk = ((l & 7) + (l >> 4) * 8) * 144 + ((l >> 3) & 1) * 16;
    const u32 offBt = ((l & 7) + ((l >> 3) & 1) * 8) * 144 + (l >> 4) * 16;

    const u32 aK  = sb + SM_K  + offBk;
    const u32 aV  = sb + SM_V  + offBt;
    const u32 aWQ = sb + SM_WQ + offBt;
    const u32 aWP = sb + SM_WP + offBt;

    u32 ax[4][4];
    {
        const int r0 = qbase + wrow + (l >> 2);
        const int c0 = (l & 3) * 2;
        const float* x0 = x + (size_t)r0 * CH + c0;
        const float* x1 = x + (size_t)(r0 + 8) * CH + c0;
        #pragma unroll
        for (int kc = 0; kc < 4; kc++) {
            float2 f00 = __ldg((const float2*)(x0 + kc * 16));
            float2 f10 = __ldg((const float2*)(x1 + kc * 16));
            float2 f01 = __ldg((const float2*)(x0 + kc * 16 + 8));
            float2 f11 = __ldg((const float2*)(x1 + kc * 16 + 8));
            ax[kc][0] = pack_h2(f00.x, f00.y);
            ax[kc][1] = pack_h2(f10.x, f10.y);
            ax[kc][2] = pack_h2(f01.x, f01.y);
            ax[kc][3] = pack_h2(f11.x, f11.y);
        }
    }
    __syncthreads();

    u32 aQ[4][4];
    #pragma unroll
    for (int ng = 0; ng < 4; ng++) {
        float C0[4] = {0.f, 0.f, 0.f, 0.f};
        float C1[4] = {0.f, 0.f, 0.f, 0.f};
        #pragma unroll
        for (int kc = 0; kc < 4; kc++) {
            u32 b0, b1, b2, b3;
            ldsm4t(b0, b1, b2, b3, aWQ + kc * 16 * 144 + ng * 32);
            mma16816(C0, ax[kc], b0, b1);
            mma16816(C1, ax[kc], b2, b3);
        }
        int col0 = ng * 16 + (l & 3) * 2;
        float q00 = __ldg(bq + col0),     q01 = __ldg(bq + col0 + 1);
        float q10 = __ldg(bq + col0 + 8), q11 = __ldg(bq + col0 + 9);
        aQ[ng][0] = pack_h2((C0[0] + q00) * QSCALE, (C0[1] + q01) * QSCALE);
        aQ[ng][1] = pack_h2((C0[2] + q00) * QSCALE, (C0[3] + q01) * QSCALE);
        aQ[ng][2] = pack_h2((C1[0] + q10) * QSCALE, (C1[1] + q11) * QSCALE);
        aQ[ng][3] = pack_h2((C1[2] + q10) * QSCALE, (C1[3] + q11) * QSCALE);
    }

    CP_WAIT0();
    __syncthreads();

    float O[8][4];
    #pragma unroll
    for (int m = 0; m < 8; m++)
        { O[m][0] = 0.f; O[m][1] = 0.f; O[m][2] = 0.f; O[m][3] = 0.f; }
    float ls0 = 0.f, ls1 = 0.f;

    #pragma unroll 2
    for (int c = 0; c < 16; c++) {
        const u32 kbase = aK + c * 16 * 144;
        const u32 vbase = aV + c * 16 * 144;
        u32 vb[4][4];
        #pragma unroll
        for (int ng = 0; ng < 4; ng++)
            ldsm4t(vb[ng][0], vb[ng][1], vb[ng][2], vb[ng][3], vbase + ng * 32);

        float S0[4] = {0.f, 0.f, 0.f, 0.f};
        float S1[4] = {0.f, 0.f, 0.f, 0.f};
        #pragma unroll
        for (int kc = 0; kc < 4; kc++) {
            u32 b0, b1, b2, b3;
            ldsm4(b0, b1, b2, b3, kbase + kc * 32);
            mma16816(S0, aQ[kc], b0, b1);
            mma16816(S1, aQ[kc], b2, b3);
        }
        u32 pA[4];
        pA[0] = ex2_h2(pack_h2(S0[0], S0[1]));
        pA[1] = ex2_h2(pack_h2(S0[2], S0[3]));
        pA[2] = ex2_h2(pack_h2(S1[0], S1[1]));
        pA[3] = ex2_h2(pack_h2(S1[2], S1[3]));
        {
            __half2 s02 = __hadd2(*(__half2*)&pA[0], *(__half2*)&pA[2]);
            __half2 s13 = __hadd2(*(__half2*)&pA[1], *(__half2*)&pA[3]);
            float2 f0 = __half22float2(s02);
            float2 f1 = __half22float2(s13);
            ls0 += f0.x + f0.y;
            ls1 += f1.x + f1.y;
        }
        #pragma unroll
        for (int ng = 0; ng < 4; ng++) {
            mma16816(O[2 * ng],     pA, vb[ng][0], vb[ng][1]);
            mma16816(O[2 * ng + 1], pA, vb[ng][2], vb[ng][3]);
        }
    }

    ls0 += __shfl_xor_sync(0xffffffffu, ls0, 1);
    ls0 += __shfl_xor_sync(0xffffffffu, ls0, 2);
    ls1 += __shfl_xor_sync(0xffffffffu, ls1, 1);
    ls1 += __shfl_xor_sync(0xffffffffu, ls1, 2);
    const float rl0 = 1.0f / ls0;
    const float rl1 = 1.0f / ls1;

    u32 aO[4][4];
    #pragma unroll
    for (int kc = 0; kc < 4; kc++) {
        aO[kc][0] = pack_h2(O[2 * kc][0] * rl0,     O[2 * kc][1] * rl0);
        aO[kc][1] = pack_h2(O[2 * kc][2] * rl1,     O[2 * kc][3] * rl1);
        aO[kc][2] = pack_h2(O[2 * kc + 1][0] * rl0, O[2 * kc + 1][1] * rl0);
        aO[kc][3] = pack_h2(O[2 * kc + 1][2] * rl1, O[2 * kc + 1][3] * rl1);
    }

    const int row0 = qbase + wrow + (l >> 2);
    #pragma unroll
    for (int ng = 0; ng < 4; ng++) {
        float C0[4] = {0.f, 0.f, 0.f, 0.f};
        float C1[4] = {0.f, 0.f, 0.f, 0.f};
        #pragma unroll
        for (int kc = 0; kc < 4; kc++) {
            u32 b0, b1, b2, b3;
            ldsm4t(b0, b1, b2, b3, aWP + kc * 16 * 144 + ng * 32);
            mma16816(C0, aO[kc], b0, b1);
            mma16816(C1, aO[kc], b2, b3);
        }
        int col0 = ng * 16 + (l & 3) * 2;
        float p00 = __ldg(bp + col0),     p01 = __ldg(bp + col0 + 1);
        float p10 = __ldg(bp + col0 + 8), p11 = __ldg(bp + col0 + 9);
        float2* o0 = (float2*)(out + (size_t)row0 * CH + col0);
        float2* o1 = (float2*)(out + (size_t)(row0 + 8) * CH + col0);
        o0[0] = make_float2(C0[0] + p00, C0[1] + p01);
        o0[4] = make_float2(C1[0] + p10, C1[1] + p11);
        o1[0] = make_float2(C0[2] + p00, C0[3] + p01);
        o1[4] = make_float2(C1[2] + p10, C1[3] + p11);
    }
}

// ---------------------------------------------------------------------------
extern "C" void kernel_launch(void* const* d_in, const int* in_sizes, int n_in,
                              void* d_out, int out_size)
{
    const float* x     = (const float*)d_in[0];
    const float* Wq    = (const float*)d_in[1];
    const float* bq    = (const float*)d_in[2];
    const float* Wk    = (const float*)d_in[3];
    const float* bk    = (const float*)d_in[4];
    const float* Wv    = (const float*)d_in[5];
    const float* bv    = (const float*)d_in[6];
    const float* Wsr   = (const float*)d_in[7];
    const float* bsr   = (const float*)d_in[8];
    const float* gamma = (const float*)d_in[9];
    const float* beta  = (const float*)d_in[10];
    const float* Wp    = (const float*)d_in[11];
    const float* bp    = (const float*)d_in[12];
    float* out = (float*)d_out;

    int B = in_sizes[0] / (NQ * CH);
    if (B > MAXB) B = MAXB;

    cudaFuncSetAttribute(conv_kernel, cudaFuncAttributeMaxDynamicSharedMemorySize, CV_SMEM);
    cudaFuncSetAttribute(attn_kernel, cudaFuncAttributeMaxDynamicSharedMemorySize, SM_TOTAL);

    wprep_kernel<<<256, 256>>>(Wsr);
    conv_kernel<<<B * 8 * 16, 256, CV_SMEM>>>(x);
    lnkv_kernel<<<B * 16, 256>>>(bsr, gamma, beta, Wk, bk, Wv, bv);
    attn_kernel<<<B * 128, 256, SM_TOTAL>>>(x, Wq, bq, Wp, bp, out);
}